// round 15
// baseline (speedup 1.0000x reference)
#include <cuda_runtime.h>
#include <cuda_bf16.h>
#include <math.h>
#include <stdint.h>

#define P_PTS     16384
#define M_PART    4096
#define HASHMAP_SZ 524288u
#define NUM_LVL   16
#define INV_SQRT2 0.70710678118654752f

// ---------------- scratch (device globals; no allocation allowed) -------------
__device__ __align__(16) float g_xin[232 * P_PTS];
__device__ __align__(16) float g_stats[7 * P_PTS];
__device__ __align__(16) __nv_bfloat16 g_x[P_PTS * 512];
__device__ __align__(16) __nv_bfloat16 g_s[P_PTS * 512];   // skip input (cols 26..255)
__device__ __align__(16) __nv_bfloat16 g_w[2304 * 512];

// ---------------- PTX helpers -------------------------------------------------
static __device__ __forceinline__ uint32_t smem_u32(const void* p) {
    uint32_t a;
    asm("{ .reg .u64 t; cvta.to.shared.u64 t, %1; cvt.u32.u64 %0, t; }" : "=r"(a) : "l"(p));
    return a;
}
static __device__ __forceinline__ void cp16(uint32_t s, const void* g) {
    asm volatile("cp.async.ca.shared.global [%0], [%1], 16;" :: "r"(s), "l"(g));
}
#define CP_COMMIT()  asm volatile("cp.async.commit_group;" ::: "memory")
#define CP_WAIT0()   asm volatile("cp.async.wait_group 0;" ::: "memory")

static __device__ __forceinline__ void ldsm4(uint32_t* r, uint32_t a) {
    asm volatile("ldmatrix.sync.aligned.m8n8.x4.shared.b16 {%0,%1,%2,%3}, [%4];"
                 : "=r"(r[0]), "=r"(r[1]), "=r"(r[2]), "=r"(r[3]) : "r"(a));
}
static __device__ __forceinline__ void mma16816(float* c, const uint32_t* a,
                                                uint32_t b0, uint32_t b1) {
    asm volatile(
        "mma.sync.aligned.m16n8k16.row.col.f32.bf16.bf16.f32 "
        "{%0,%1,%2,%3}, {%4,%5,%6,%7}, {%8,%9}, {%0,%1,%2,%3};"
        : "+f"(c[0]), "+f"(c[1]), "+f"(c[2]), "+f"(c[3])
        : "r"(a[0]), "r"(a[1]), "r"(a[2]), "r"(a[3]), "r"(b0), "r"(b1));
}
static __device__ __forceinline__ float softplus100(float v) {
    float y = 100.0f * v;
    return (fmaxf(y, 0.0f) + __logf(1.0f + __expf(-fabsf(y)))) * 0.01f;
}

struct WPtrs { const float* w[9]; };
struct BPtrs { const float* b[9]; };

// ---------------- ball query + fused weight prep ------------------------------
__global__ __launch_bounds__(256)
void ball_prep_kernel(const float* __restrict__ inp,
                      const float* __restrict__ parts,
                      float* __restrict__ stats,
                      WPtrs wp, __nv_bfloat16* __restrict__ wout)
{
    {
        const int cum[10]  = {0, 256, 512, 768, 896, 1152, 1408, 1664, 1920, 2304};
        const int nout[9]  = {256, 256, 256, 26, 256, 256, 256, 256, 257};
        const int kact[9]  = {230, 256, 256, 256, 256, 256, 256, 256, 256};
        int gid = blockIdx.x * 256 + threadIdx.x;
#pragma unroll
        for (int t9 = 0; t9 < 9; ++t9) {
            int i = gid + t9 * 65536;
            int r = i >> 8, k = i & 255;
            int l = 0;
#pragma unroll
            for (int t = 1; t < 9; ++t) if (r >= cum[t]) l = t;
            int n = r - cum[l];
            float v = (n < nout[l] && k < kact[l]) ? wp.w[l][n * kact[l] + k] : 0.0f;
            __nv_bfloat16 h = __float2bfloat16(v);
            wout[(size_t)r * 512 + k]       = h;
            wout[(size_t)r * 512 + 256 + k] = __float2bfloat16(v - __bfloat162float(h));
        }
    }

    extern __shared__ float fsm[];
    float4* sp4 = (float4*)fsm;
    float*  ex  = fsm + 16384;
    int tid = threadIdx.x;
    for (int i = tid; i < M_PART; i += 256) {
        float px = parts[3 * i], py = parts[3 * i + 1], pz = parts[3 * i + 2];
        sp4[i] = make_float4(px, py, pz, (px * px + py * py) + pz * pz);
    }
    __syncthreads();

    const int c  = tid >> 6;
    const int pl = tid & 63;
    const int p  = blockIdx.x * 64 + pl;
    const float x = inp[3 * p], y = inp[3 * p + 1], z = inp[3 * p + 2];
    const float q1 = (x * x + y * y) + z * z;
    const float R2 = 0.01f;
    const int j0 = c << 10, j1 = j0 + 1024;

    int h = 0;
    float wsum = 0.f, swx = 0.f, swy = 0.f, swz = 0.f;
    float sdx = 0.f, sdy = 0.f, sdz = 0.f;
    float s2x = 0.f, s2y = 0.f, s2z = 0.f;
#pragma unroll 8
    for (int j = j0; j < j1; ++j) {
        float4 q = sp4[j];
        float dot = x * q.x + y * q.y + z * q.z;
        float d2e = (q1 + q.w) - 2.0f * dot;
        if (d2e < R2) {
            ++h;
            float dx = q.x - x, dy = q.y - y, dz = q.z - z;
            float d2 = dx * dx + dy * dy + dz * dz;
            float d  = sqrtf(fmaxf(d2, 1e-24f));
            float dr = d / 0.1f;
            float w  = fmaxf(1.0f - dr * dr * dr, 0.0f);
            wsum += w;
            swx = fmaf(w, q.x, swx); swy = fmaf(w, q.y, swy); swz = fmaf(w, q.z, swz);
            sdx += dx; sdy += dy; sdz += dz;
            s2x = fmaf(dx, dx, s2x); s2y = fmaf(dy, dy, s2y); s2z = fmaf(dz, dz, s2z);
        }
    }
    ex[c * 64 + pl] = (float)h;
    __syncthreads();
    int h0 = (int)ex[pl], h1 = (int)ex[64 + pl], h2 = (int)ex[128 + pl], h3 = (int)ex[192 + pl];
    int start = (c > 0 ? h0 : 0) + (c > 1 ? h1 : 0) + (c > 2 ? h2 : 0);
    int total = h0 + h1 + h2 + h3;
    int cnt   = min(32, total);
    int budget = max(0, min(32 - start, h));
    if (budget < h) {
        wsum = swx = swy = swz = 0.f;
        sdx = sdy = sdz = 0.f;
        s2x = s2y = s2z = 0.f;
        int taken = 0;
        for (int j = j0; j < j1 && taken < budget; ++j) {
            float4 q = sp4[j];
            float dot = x * q.x + y * q.y + z * q.z;
            float d2e = (q1 + q.w) - 2.0f * dot;
            if (d2e < R2) {
                ++taken;
                float dx = q.x - x, dy = q.y - y, dz = q.z - z;
                float d2 = dx * dx + dy * dy + dz * dz;
                float d  = sqrtf(fmaxf(d2, 1e-24f));
                float dr = d / 0.1f;
                float w  = fmaxf(1.0f - dr * dr * dr, 0.0f);
                wsum += w;
                swx = fmaf(w, q.x, swx); swy = fmaf(w, q.y, swy); swz = fmaf(w, q.z, swz);
                sdx += dx; sdy += dy; sdz += dz;
                s2x = fmaf(dx, dx, s2x); s2y = fmaf(dy, dy, s2y); s2z = fmaf(dz, dz, s2z);
            }
        }
    }
    __syncthreads();
    float part[10] = {wsum, swx, swy, swz, sdx, sdy, sdz, s2x, s2y, s2z};
#pragma unroll
    for (int f = 0; f < 10; ++f) ex[f * 256 + c * 64 + pl] = part[f];
    __syncthreads();

    if (c == 0) {
        float S[10];
#pragma unroll
        for (int f = 0; f < 10; ++f)
            S[f] = ((ex[f * 256 + pl] + ex[f * 256 + 64 + pl])
                  + ex[f * 256 + 128 + pl]) + ex[f * 256 + 192 + pl];
        int ninv = 32 - cnt;
        if (ninv > 0) {
            float d  = sqrtf(fmaxf(q1, 1e-24f));
            float dr = d / 0.1f;
            float w  = fmaxf(1.0f - dr * dr * dr, 0.0f);
            S[0] += (float)ninv * w;
        }
        float nf  = (float)cnt;
        float wdn = S[0] + 1e-12f;
        float den = nf + 1e-12f;
        float vmx = S[4] / den, vmy = S[5] / den, vmz = S[6] / den;
        stats[0 * P_PTS + p] = S[0];
        stats[1 * P_PTS + p] = S[1] / wdn;
        stats[2 * P_PTS + p] = S[2] / wdn;
        stats[3 * P_PTS + p] = S[3] / wdn;
        stats[4 * P_PTS + p] = (S[7] - 2.0f * vmx * S[4] + nf * vmx * vmx) / den;
        stats[5 * P_PTS + p] = (S[8] - 2.0f * vmy * S[5] + nf * vmy * vmy) / den;
        stats[6 * P_PTS + p] = (S[9] - 2.0f * vmz * S[6] + nf * vmz * vmz) / den;
    }
}

// ---------------- encode (unchanged, passing) ----------------------------------
__device__ __forceinline__ void penc3(float* __restrict__ xin, int p, int base,
                                      float a, float b, float c)
{
    xin[(base + 0) * P_PTS + p] = a;
    xin[(base + 1) * P_PTS + p] = b;
    xin[(base + 2) * P_PTS + p] = c;
    float v[3] = {a, b, c};
#pragma unroll
    for (int f = 0; f < 10; ++f) {
        float fr = (float)(1 << f);
#pragma unroll
        for (int ch = 0; ch < 3; ++ch) {
            float s, co;
            sincosf(v[ch] * fr, &s, &co);
            xin[(base + 3 + f * 6 + ch)     * P_PTS + p] = s;
            xin[(base + 3 + f * 6 + 3 + ch) * P_PTS + p] = co;
        }
    }
}

__global__ __launch_bounds__(256)
void encode_kernel(const float* __restrict__ inp,
                   const float* __restrict__ table,
                   const float* __restrict__ stats,
                   float* __restrict__ xin)
{
    int tid = threadIdx.x;
    int pl = tid & 31, s = tid >> 5;
    int p = blockIdx.x * 32 + pl;
    float x = inp[3 * p], y = inp[3 * p + 1], z = inp[3 * p + 2];

    if (s < 4) {
        float xn[3] = { (x / 1.5f + 1.0f) * 0.5f,
                        (y / 1.5f + 1.0f) * 0.5f,
                        (z / 1.5f + 1.0f) * 0.5f };
#pragma unroll 1
        for (int li = 0; li < 4; ++li) {
            int l = s * 4 + li;
            double scd   = exp2((7.0 * (double)l) / 15.0) * 16.0 - 1.0;
            float  scale = (float)scd;
            unsigned res = (unsigned)ceil(scd) + 1u;
            bool dense   = ((unsigned long long)res * res * res <= (unsigned long long)HASHMAP_SZ);
            unsigned pg[3]; float fr[3];
#pragma unroll
            for (int cc = 0; cc < 3; ++cc) {
                float pos = fmaf(xn[cc], scale, 0.5f);
                float pf  = floorf(pos);
                fr[cc] = pos - pf;
                pg[cc] = (unsigned)pf;
            }
            float wx[2] = {1.f - fr[0], fr[0]};
            float wy[2] = {1.f - fr[1], fr[1]};
            float wz[2] = {1.f - fr[2], fr[2]};
            const float2* tbl = (const float2*)table + (size_t)l * HASHMAP_SZ;
            float f0 = 0.f, f1 = 0.f;
#pragma unroll
            for (int cc = 0; cc < 8; ++cc) {
                unsigned gx = pg[0] + (unsigned)(cc & 1);
                unsigned gy = pg[1] + (unsigned)((cc >> 1) & 1);
                unsigned gz = pg[2] + (unsigned)((cc >> 2) & 1);
                unsigned idx;
                if (dense) idx = gx + gy * res + gz * res * res;
                else       idx = ((gx * 1u) ^ (gy * 2654435761u) ^ (gz * 805459861u)) & (HASHMAP_SZ - 1u);
                float w = (wx[cc & 1] * wy[(cc >> 1) & 1]) * wz[(cc >> 2) & 1];
                float2 t = tbl[idx];
                f0 = fmaf(w, t.x, f0);
                f1 = fmaf(w, t.y, f1);
            }
            xin[(198 + 2 * l) * P_PTS + p] = f0;
            xin[(199 + 2 * l) * P_PTS + p] = f1;
        }
    } else if (s == 4) {
        penc3(xin, p, 0, x, y, z);
    } else if (s == 5) {
        float wsum = stats[p];
        xin[63 * P_PTS + p] = wsum;
#pragma unroll
        for (int f = 0; f < 4; ++f) {
            float sn, co;
            sincosf(wsum * (float)(1 << f), &sn, &co);
            xin[(64 + 2 * f) * P_PTS + p] = sn;
            xin[(65 + 2 * f) * P_PTS + p] = co;
        }
        xin[230 * P_PTS + p] = 0.0f;
        xin[231 * P_PTS + p] = 0.0f;
    } else if (s == 6) {
        penc3(xin, p, 72, stats[1 * P_PTS + p], stats[2 * P_PTS + p], stats[3 * P_PTS + p]);
    } else {
        penc3(xin, p, 135, stats[4 * P_PTS + p], stats[5 * P_PTS + p], stats[6 * P_PTS + p]);
    }
}

// ---------------- fused transpose + bf16-split: xin -> g_x AND g_s ------------
__global__ void conv_tr2(const float* __restrict__ src,
                         __nv_bfloat16* __restrict__ dx,
                         __nv_bfloat16* __restrict__ ds)
{
    __shared__ float s[32][33];
    int tx = threadIdx.x, ty = threadIdx.y;
    int ct = blockIdx.x, pt = blockIdx.y;
#pragma unroll
    for (int r2 = 0; r2 < 4; ++r2) {
        int ci = ty + r2 * 8;
        int c = ct * 32 + ci;
        int p = pt * 32 + tx;
        s[ci][tx] = (c < 232) ? src[(size_t)c * P_PTS + p] : 0.0f;
    }
    __syncthreads();
#pragma unroll
    for (int r2 = 0; r2 < 4; ++r2) {
        int pi = ty + r2 * 8;
        int p = pt * 32 + pi;
        int c = ct * 32 + tx;
        float v = s[tx][pi];
        __nv_bfloat16 h = __float2bfloat16(v);
        dx[(size_t)p * 512 + c]       = h;
        dx[(size_t)p * 512 + 256 + c] = __float2bfloat16(v - __bfloat162float(h));
        if (c < 230) {
            float vs = v * INV_SQRT2;
            __nv_bfloat16 hs = __float2bfloat16(vs);
            ds[(size_t)p * 512 + c + 26]       = hs;
            ds[(size_t)p * 512 + 256 + c + 26] = __float2bfloat16(vs - __bfloat162float(hs));
        }
    }
}

// ---------------- fused persistent MLP: M=64, 2 CTAs/SM (desync) -------------
// per-CTA smem: LOW0 [0,32K), LOW1 [32K,64K), HIGH [64K,96K), W [96K,112K)
// act region = 4 chunk-tiles hi (4KB each) then 4 lo (4KB each)
#define R_LOW0 0
#define R_LOW1 32768
#define R_HIGH 65536
#define R_W    98304
#define SMEM_FUSED 114688

__global__ __launch_bounds__(256, 2)
void fused_mlp(const __nv_bfloat16* __restrict__ gx,
               const __nv_bfloat16* __restrict__ gs,
               const __nv_bfloat16* __restrict__ gw,
               BPtrs bp, float* __restrict__ out)
{
    extern __shared__ __align__(16) char smem[];
    const uint32_t s0 = smem_u32(smem);
    const int tid = threadIdx.x, warp = tid >> 5, lane = tid & 31;
    const int wm = warp & 1, wn = warp >> 1;          // 2x4 warp grid, tile 32x32
    const int m0 = blockIdx.x << 6;

    const int rbase = tid >> 2, cc = tid & 3;          // 256 thr = 64 rows x 4
    const uint32_t so0 = (uint32_t)(rbase * 64) +
                         (((uint32_t)cc ^ (((uint32_t)rbase >> 1) & 3)) << 4);

    const int lrow = lane & 15;
    const uint32_t lhi = (uint32_t)(lane >> 4);
    uint32_t rowA[2], rqA[2], rowB[2], rqB[2];
#pragma unroll
    for (int mi = 0; mi < 2; ++mi) {
        int R = wm * 32 + mi * 16 + lrow;              // 0..63
        rowA[mi] = (uint32_t)(R * 64); rqA[mi] = (uint32_t)((R >> 1) & 3);
    }
#pragma unroll
    for (int nb = 0; nb < 2; ++nb) {
        int R = wn * 32 + nb * 16 + lrow;              // 0..127 (W tile rows)
        rowB[nb] = (uint32_t)(R * 64); rqB[nb] = (uint32_t)((R >> 1) & 3);
    }

    auto load_full_act = [&](const __nv_bfloat16* src, uint32_t lowR) {
        const __nv_bfloat16* pS = src + (size_t)(m0 + rbase) * 512 + cc * 8;
#pragma unroll
        for (int kc = 0; kc < 8; ++kc) {
            uint32_t hiT = (kc < 4) ? (lowR + (uint32_t)kc * 4096)
                                    : (R_HIGH + (uint32_t)(kc - 4) * 4096);
            int k32 = kc << 5;
            cp16(s0 + hiT + so0,         pS + k32);
            cp16(s0 + hiT + 16384 + so0, pS + 256 + k32);
        }
    };
    // W chunk: 128 N-rows x 32 K, hi 8KB + lo 8KB, single stage
    auto load_w = [&](const __nv_bfloat16* Wl, int n0w, int kc) {
        const __nv_bfloat16* pW = Wl + (size_t)(n0w + rbase) * 512 + cc * 8;
        uint32_t wb = s0 + R_W;
        int k32 = kc << 5;
        cp16(wb + so0,               pW + k32);
        cp16(wb + so0 + 4096,        pW + 64 * 512 + k32);
        cp16(wb + 8192 + so0,        pW + 256 + k32);
        cp16(wb + 8192 + so0 + 4096, pW + 64 * 512 + 256 + k32);
    };

    float c[2][4][4];
    uint32_t aF[3][8], bF[2][8];

    auto ldA = [&](int buf, uint32_t tile, int ks) {
        uint32_t ch = (uint32_t)(2 * ks) + lhi;
        ldsm4(&aF[buf][0], tile + rowA[0] + ((ch ^ rqA[0]) << 4));
        ldsm4(&aF[buf][4], tile + rowA[1] + ((ch ^ rqA[1]) << 4));
    };
    auto ldB = [&](int buf, uint32_t tile, int ks) {
        uint32_t ch = (uint32_t)(2 * ks) + lhi;
        ldsm4(&bF[buf][0], tile + rowB[0] + ((ch ^ rqB[0]) << 4));
        ldsm4(&bF[buf][4], tile + rowB[1] + ((ch ^ rqB[1]) << 4));
    };
    auto mmaBlk = [&](int abuf, int bbuf) {
#pragma unroll
        for (int mi = 0; mi < 2; ++mi)
#pragma unroll
            for (int nb = 0; nb < 2; ++nb) {
                mma16816(c[mi][nb * 2],     &aF[abuf][mi * 4],
                         bF[bbuf][nb * 4 + 0], bF[bbuf][nb * 4 + 2]);
                mma16816(c[mi][nb * 2 + 1], &aF[abuf][mi * 4],
                         bF[bbuf][nb * 4 + 1], bF[bbuf][nb * 4 + 3]);
            }
    };

    auto run_half = [&](const __nv_bfloat16* Wl, int n0w, uint32_t lowR) {
#pragma unroll
        for (int mi = 0; mi < 2; ++mi)
#pragma unroll
            for (int nf = 0; nf < 4; ++nf)
#pragma unroll
                for (int r = 0; r < 4; ++r) c[mi][nf][r] = 0.0f;
        load_w(Wl, n0w, 0); CP_COMMIT();
#pragma unroll 1
        for (int kc = 0; kc < 8; ++kc) {
            CP_WAIT0();
            __syncthreads();                       // W stage ready for all
            uint32_t tHI = s0 + ((kc < 4) ? (lowR + (uint32_t)kc * 4096)
                                          : (R_HIGH + (uint32_t)(kc - 4) * 4096));
            uint32_t tLO = tHI + 16384;
            uint32_t wst = s0 + R_W;
            uint32_t wlo = wst + 8192;
            ldB(0, wst, 0);          // WHI0
            ldA(0, tHI, 0);          // AHI0 (cached)
            ldA(2, tLO, 0);          // ALO0
            mmaBlk(0, 0);            // s0
            ldB(1, wst, 1);          // WHI1
            ldA(1, tHI, 1);          // AHI1 (cached)
            mmaBlk(2, 0);            // s1
            ldA(2, tLO, 1);          // ALO1
            mmaBlk(1, 1);            // s2
            ldB(0, wlo, 0);          // WLO0
            mmaBlk(2, 1);            // s3
            ldB(1, wlo, 1);          // WLO1
            mmaBlk(0, 0);            // s4
            mmaBlk(1, 1);            // s5
            __syncthreads();                       // all reads of W done
            if (kc + 1 < 8) { load_w(Wl, n0w, kc + 1); CP_COMMIT(); }
        }
    };

    auto epi_smem = [&](uint32_t destR, const float* bias, int nb0, float os, int validN) {
#pragma unroll
        for (int mi = 0; mi < 2; ++mi)
#pragma unroll
            for (int nf = 0; nf < 4; ++nf) {
                int ncol = wn * 32 + nf * 8 + ((lane & 3) << 1);
                if (ncol >= validN) continue;
                float b0 = __ldg(bias + nb0 + ncol);
                float b1 = __ldg(bias + nb0 + ncol + 1);
                uint32_t chunk = (uint32_t)ncol >> 5;
                uint32_t cpos  = (uint32_t)ncol & 31;
#pragma unroll
                for (int r2 = 0; r2 < 2; ++r2) {
                    int row = wm * 32 + mi * 16 + (lane >> 2) + r2 * 8;   // 0..63
                    float v0 = softplus100(c[mi][nf][r2 * 2 + 0] + b0) * os;
                    float v1 = softplus100(c[mi][nf][r2 * 2 + 1] + b1) * os;
                    __nv_bfloat16 h0 = __float2bfloat16(v0);
                    __nv_bfloat16 h1 = __float2bfloat16(v1);
                    __nv_bfloat16 l0 = __float2bfloat16(v0 - __bfloat162float(h0));
                    __nv_bfloat16 l1 = __float2bfloat16(v1 - __bfloat162float(h1));
                    uint32_t hw = (uint32_t)__bfloat16_as_ushort(h0) |
                                  ((uint32_t)__bfloat16_as_ushort(h1) << 16);
                    uint32_t lw = (uint32_t)__bfloat16_as_ushort(l0) |
                                  ((uint32_t)__bfloat16_as_ushort(l1) << 16);
                    uint32_t off = (uint32_t)(row * 64) +
                                   (((cpos >> 3) ^ (((uint32_t)row >> 1) & 3)) << 4) +
                                   ((cpos & 7) << 1);
                    *(uint32_t*)(smem + destR + chunk * 4096 + off)         = hw;
                    *(uint32_t*)(smem + destR + 16384 + chunk * 4096 + off) = lw;
                }
            }
    };

    auto epi_gmem = [&](int n0w, const float* bias) {
#pragma unroll
        for (int mi = 0; mi < 2; ++mi)
#pragma unroll
            for (int nf = 0; nf < 4; ++nf) {
                int n = n0w + wn * 32 + nf * 8 + ((lane & 3) << 1);
                float b0 = __ldg(bias + n);
                float b1 = __ldg(bias + n + 1);
#pragma unroll
                for (int r2 = 0; r2 < 2; ++r2) {
                    int row = wm * 32 + mi * 16 + (lane >> 2) + r2 * 8;
                    size_t m = (size_t)(m0 + row);
                    out[m * 257 + n]     = c[mi][nf][r2 * 2 + 0] + b0;
                    out[m * 257 + n + 1] = c[mi][nf][r2 * 2 + 1] + b1;
                }
            }
    };

    // ---- initial activation load ----
    load_full_act(gx, R_LOW0); CP_COMMIT(); CP_WAIT0(); __syncthreads();
    uint32_t lowR = R_LOW0, altR = R_LOW1;
    const int wrow[9] = {0, 256, 512, 768, 896, 1152, 1408, 1664, 1920};

#pragma unroll 1
    for (int l = 0; l < 9; ++l) {
        const __nv_bfloat16* Wl = gw + (size_t)wrow[l] * 512;
        const float* bias = bp.b[l];
        if (l == 8) {
            run_half(Wl, 0, lowR);
            epi_gmem(0, bias);
            run_half(Wl, 128, lowR);
            epi_gmem(128, bias);
            // ---- column 256 via bf16x3 scalar dot from resident smem ----
            __syncthreads();
            ((uint32_t*)(smem + R_W))[tid] =
                ((const uint32_t*)(gw + (size_t)2176 * 512))[tid];
            __syncthreads();
            {
                int r  = tid >> 2;           // 0..63
                int kq = tid & 3;            // 2 chunks each
                float acc = 0.0f;
                uint32_t rq = ((uint32_t)r >> 1) & 3;
#pragma unroll 1
                for (int c2 = 0; c2 < 2; ++c2) {
                    int kc = kq * 2 + c2;
                    uint32_t base = (kc < 4) ? (lowR + (uint32_t)kc * 4096)
                                             : (R_HIGH + (uint32_t)(kc - 4) * 4096);
#pragma unroll
                    for (int j = 0; j < 32; ++j) {
                        int col = kc * 32 + j;
                        uint32_t off = (uint32_t)(r * 64) +
                                       ((((uint32_t)j >> 3) ^ rq) << 4) + ((j & 7) << 1);
                        float ahi = __bfloat162float(*(__nv_bfloat16*)(smem + base + off));
                        float alo = __bfloat162float(*(__nv_bfloat16*)(smem + base + 16384 + off));
                        float whi = __bfloat162float(*(__nv_bfloat16*)(smem + R_W + col * 2));
                        float wlo = __bfloat162float(*(__nv_bfloat16*)(smem + R_W + 512 + col * 2));
                        acc = fmaf(ahi, whi, acc);
                        acc = fmaf(alo, whi, acc);
                        acc = fmaf(ahi, wlo, acc);
                    }
                }
                acc += __shfl_xor_sync(0xFFFFFFFFu, acc, 1);
                acc += __shfl_xor_sync(0xFFFFFFFFu, acc, 2);
                if (kq == 0)
                    out[(size_t)(m0 + r) * 257 + 256] = acc + __ldg(bias + 256);
            }
        } else if (l == 3) {
            run_half(Wl, 0, lowR);
            __syncthreads();
            load_full_act(gs, altR); CP_COMMIT(); CP_WAIT0(); __syncthreads();
            epi_smem(altR, bias, 0, INV_SQRT2, 26);
            __syncthreads();
            uint32_t t = lowR; lowR = altR; altR = t;
        } else {
            run_half(Wl, 0, lowR);
            epi_smem(altR, bias, 0, 1.0f, 128);    // altR dead; disjoint from reads
            run_half(Wl, 128, lowR);
            __syncthreads();                       // all reads of HIGH done
            epi_smem(R_HIGH, bias, 128, 1.0f, 128);
            __syncthreads();
            uint32_t t = lowR; lowR = altR; altR = t;
        }
    }
}

// ---------------- launch ------------------------------------------------------
extern "C" void kernel_launch(void* const* d_in, const int* in_sizes, int n_in,
                              void* d_out, int out_size)
{
    const float* inp   = (const float*)d_in[0];
    const float* parts = (const float*)d_in[1];
    const float* table = (const float*)d_in[2];
    WPtrs wp;
    BPtrs bp;
    for (int l = 0; l < 9; ++l) {
        wp.w[l] = (const float*)d_in[3 + 2 * l];
        bp.b[l] = (const float*)d_in[4 + 2 * l];
    }

    float *xin, *st;
    __nv_bfloat16 *xb, *sb, *wbase;
    cudaGetSymbolAddress((void**)&xin, g_xin);
    cudaGetSymbolAddress((void**)&st,  g_stats);
    cudaGetSymbolAddress((void**)&xb, g_x);
    cudaGetSymbolAddress((void**)&sb, g_s);
    cudaGetSymbolAddress((void**)&wbase, g_w);

    const int BQ_SMEM = (16384 + 2560) * 4;
    cudaFuncSetAttribute(fused_mlp, cudaFuncAttributeMaxDynamicSharedMemorySize, SMEM_FUSED);
    cudaFuncSetAttribute(ball_prep_kernel, cudaFuncAttributeMaxDynamicSharedMemorySize, BQ_SMEM);

    ball_prep_kernel<<<P_PTS / 64, 256, BQ_SMEM>>>(inp, parts, st, wp, wbase);  // idx 0
    encode_kernel<<<P_PTS / 32, 256>>>(inp, table, st, xin);                    // idx 1
    conv_tr2<<<dim3(8, P_PTS / 32), dim3(32, 8)>>>(xin, xb, sb);                // idx 2
    fused_mlp<<<P_PTS / 64, 256, SMEM_FUSED>>>(xb, sb, wbase, bp, (float*)d_out); // idx 3
}

// round 16
// speedup vs baseline: 1.0158x; 1.0158x over previous
#include <cuda_runtime.h>
#include <cuda_bf16.h>
#include <math.h>
#include <stdint.h>

#define P_PTS     16384
#define M_PART    4096
#define HASHMAP_SZ 524288u
#define NUM_LVL   16
#define INV_SQRT2 0.70710678118654752f

// ---------------- scratch (device globals; no allocation allowed) -------------
__device__ __align__(16) float g_xin[232 * P_PTS];
__device__ __align__(16) float g_stats[7 * P_PTS];
__device__ __align__(16) __nv_bfloat16 g_x[P_PTS * 512];
__device__ __align__(16) __nv_bfloat16 g_s[P_PTS * 512];   // skip input (cols 26..255)
__device__ __align__(16) __nv_bfloat16 g_w[2304 * 512];

// ---------------- PTX helpers -------------------------------------------------
static __device__ __forceinline__ uint32_t smem_u32(const void* p) {
    uint32_t a;
    asm("{ .reg .u64 t; cvta.to.shared.u64 t, %1; cvt.u32.u64 %0, t; }" : "=r"(a) : "l"(p));
    return a;
}
static __device__ __forceinline__ void cp16(uint32_t s, const void* g) {
    asm volatile("cp.async.ca.shared.global [%0], [%1], 16;" :: "r"(s), "l"(g));
}
#define CP_COMMIT()  asm volatile("cp.async.commit_group;" ::: "memory")
#define CP_WAIT0()   asm volatile("cp.async.wait_group 0;" ::: "memory")

static __device__ __forceinline__ void ldsm4(uint32_t* r, uint32_t a) {
    asm volatile("ldmatrix.sync.aligned.m8n8.x4.shared.b16 {%0,%1,%2,%3}, [%4];"
                 : "=r"(r[0]), "=r"(r[1]), "=r"(r[2]), "=r"(r[3]) : "r"(a));
}
static __device__ __forceinline__ void mma16816(float* c, const uint32_t* a,
                                                uint32_t b0, uint32_t b1) {
    asm volatile(
        "mma.sync.aligned.m16n8k16.row.col.f32.bf16.bf16.f32 "
        "{%0,%1,%2,%3}, {%4,%5,%6,%7}, {%8,%9}, {%0,%1,%2,%3};"
        : "+f"(c[0]), "+f"(c[1]), "+f"(c[2]), "+f"(c[3])
        : "r"(a[0]), "r"(a[1]), "r"(a[2]), "r"(a[3]), "r"(b0), "r"(b1));
}
static __device__ __forceinline__ float softplus100(float v) {
    float y = 100.0f * v;
    return (fmaxf(y, 0.0f) + __logf(1.0f + __expf(-fabsf(y)))) * 0.01f;
}

struct WPtrs { const float* w[9]; };
struct BPtrs { const float* b[9]; };

// ---------------- ball query (8x32 split) + fused weight prep -----------------
__global__ __launch_bounds__(256)
void ball_prep_kernel(const float* __restrict__ inp,
                      const float* __restrict__ parts,
                      float* __restrict__ stats,
                      WPtrs wp, __nv_bfloat16* __restrict__ wout)
{
    // ---- weight prep (blocks 0..255 only): 9 elements per thread ----
    if (blockIdx.x < 256) {
        const int cum[10]  = {0, 256, 512, 768, 896, 1152, 1408, 1664, 1920, 2304};
        const int nout[9]  = {256, 256, 256, 26, 256, 256, 256, 256, 257};
        const int kact[9]  = {230, 256, 256, 256, 256, 256, 256, 256, 256};
        int gid = blockIdx.x * 256 + threadIdx.x;
#pragma unroll
        for (int t9 = 0; t9 < 9; ++t9) {
            int i = gid + t9 * 65536;
            int r = i >> 8, k = i & 255;
            int l = 0;
#pragma unroll
            for (int t = 1; t < 9; ++t) if (r >= cum[t]) l = t;
            int n = r - cum[l];
            float v = (n < nout[l] && k < kact[l]) ? wp.w[l][n * kact[l] + k] : 0.0f;
            __nv_bfloat16 h = __float2bfloat16(v);
            wout[(size_t)r * 512 + k]       = h;
            wout[(size_t)r * 512 + 256 + k] = __float2bfloat16(v - __bfloat162float(h));
        }
    }

    extern __shared__ float fsm[];             // sp4 16384 floats, ex 2560 floats
    float4* sp4 = (float4*)fsm;
    float*  ex  = fsm + 16384;
    int tid = threadIdx.x;
    for (int i = tid; i < M_PART; i += 256) {
        float px = parts[3 * i], py = parts[3 * i + 1], pz = parts[3 * i + 2];
        sp4[i] = make_float4(px, py, pz, (px * px + py * py) + pz * pz);
    }
    __syncthreads();

    const int c  = tid >> 5;                   // chunk 0..7 (512 particles each)
    const int pl = tid & 31;
    const int p  = blockIdx.x * 32 + pl;
    const float x = inp[3 * p], y = inp[3 * p + 1], z = inp[3 * p + 2];
    const float q1 = (x * x + y * y) + z * z;
    const float R2 = 0.01f;
    const int j0 = c << 9, j1 = j0 + 512;

    int h = 0;
    float wsum = 0.f, swx = 0.f, swy = 0.f, swz = 0.f;
    float sdx = 0.f, sdy = 0.f, sdz = 0.f;
    float s2x = 0.f, s2y = 0.f, s2z = 0.f;
#pragma unroll 8
    for (int j = j0; j < j1; ++j) {
        float4 q = sp4[j];
        float dot = x * q.x + y * q.y + z * q.z;
        float d2e = (q1 + q.w) - 2.0f * dot;
        if (d2e < R2) {
            ++h;
            float dx = q.x - x, dy = q.y - y, dz = q.z - z;
            float d2 = dx * dx + dy * dy + dz * dz;
            float d  = sqrtf(fmaxf(d2, 1e-24f));
            float dr = d / 0.1f;
            float w  = fmaxf(1.0f - dr * dr * dr, 0.0f);
            wsum += w;
            swx = fmaf(w, q.x, swx); swy = fmaf(w, q.y, swy); swz = fmaf(w, q.z, swz);
            sdx += dx; sdy += dy; sdz += dz;
            s2x = fmaf(dx, dx, s2x); s2y = fmaf(dy, dy, s2y); s2z = fmaf(dz, dz, s2z);
        }
    }
    ex[c * 32 + pl] = (float)h;
    __syncthreads();
    int start = 0, total = 0;
#pragma unroll
    for (int cc2 = 0; cc2 < 8; ++cc2) {
        int hv = (int)ex[cc2 * 32 + pl];
        if (cc2 < c) start += hv;
        total += hv;
    }
    int cnt    = min(32, total);
    int budget = max(0, min(32 - start, h));
    if (budget < h) {
        wsum = swx = swy = swz = 0.f;
        sdx = sdy = sdz = 0.f;
        s2x = s2y = s2z = 0.f;
        int taken = 0;
        for (int j = j0; j < j1 && taken < budget; ++j) {
            float4 q = sp4[j];
            float dot = x * q.x + y * q.y + z * q.z;
            float d2e = (q1 + q.w) - 2.0f * dot;
            if (d2e < R2) {
                ++taken;
                float dx = q.x - x, dy = q.y - y, dz = q.z - z;
                float d2 = dx * dx + dy * dy + dz * dz;
                float d  = sqrtf(fmaxf(d2, 1e-24f));
                float dr = d / 0.1f;
                float w  = fmaxf(1.0f - dr * dr * dr, 0.0f);
                wsum += w;
                swx = fmaf(w, q.x, swx); swy = fmaf(w, q.y, swy); swz = fmaf(w, q.z, swz);
                sdx += dx; sdy += dy; sdz += dz;
                s2x = fmaf(dx, dx, s2x); s2y = fmaf(dy, dy, s2y); s2z = fmaf(dz, dz, s2z);
            }
        }
    }
    __syncthreads();
    float part[10] = {wsum, swx, swy, swz, sdx, sdy, sdz, s2x, s2y, s2z};
#pragma unroll
    for (int f = 0; f < 10; ++f) ex[f * 256 + c * 32 + pl] = part[f];
    __syncthreads();

    if (c == 0) {
        float S[10];
#pragma unroll
        for (int f = 0; f < 10; ++f) {
            float acc = ex[f * 256 + pl];
#pragma unroll
            for (int cc2 = 1; cc2 < 8; ++cc2) acc += ex[f * 256 + cc2 * 32 + pl];
            S[f] = acc;
        }
        int ninv = 32 - cnt;
        if (ninv > 0) {
            float d  = sqrtf(fmaxf(q1, 1e-24f));
            float dr = d / 0.1f;
            float w  = fmaxf(1.0f - dr * dr * dr, 0.0f);
            S[0] += (float)ninv * w;
        }
        float nf  = (float)cnt;
        float wdn = S[0] + 1e-12f;
        float den = nf + 1e-12f;
        float vmx = S[4] / den, vmy = S[5] / den, vmz = S[6] / den;
        stats[0 * P_PTS + p] = S[0];
        stats[1 * P_PTS + p] = S[1] / wdn;
        stats[2 * P_PTS + p] = S[2] / wdn;
        stats[3 * P_PTS + p] = S[3] / wdn;
        stats[4 * P_PTS + p] = (S[7] - 2.0f * vmx * S[4] + nf * vmx * vmx) / den;
        stats[5 * P_PTS + p] = (S[8] - 2.0f * vmy * S[5] + nf * vmy * vmy) / den;
        stats[6 * P_PTS + p] = (S[9] - 2.0f * vmz * S[6] + nf * vmz * vmz) / den;
    }
}

// ---------------- encode (unchanged, passing) ----------------------------------
__device__ __forceinline__ void penc3(float* __restrict__ xin, int p, int base,
                                      float a, float b, float c)
{
    xin[(base + 0) * P_PTS + p] = a;
    xin[(base + 1) * P_PTS + p] = b;
    xin[(base + 2) * P_PTS + p] = c;
    float v[3] = {a, b, c};
#pragma unroll
    for (int f = 0; f < 10; ++f) {
        float fr = (float)(1 << f);
#pragma unroll
        for (int ch = 0; ch < 3; ++ch) {
            float s, co;
            sincosf(v[ch] * fr, &s, &co);
            xin[(base + 3 + f * 6 + ch)     * P_PTS + p] = s;
            xin[(base + 3 + f * 6 + 3 + ch) * P_PTS + p] = co;
        }
    }
}

__global__ __launch_bounds__(256)
void encode_kernel(const float* __restrict__ inp,
                   const float* __restrict__ table,
                   const float* __restrict__ stats,
                   float* __restrict__ xin)
{
    int tid = threadIdx.x;
    int pl = tid & 31, s = tid >> 5;
    int p = blockIdx.x * 32 + pl;
    float x = inp[3 * p], y = inp[3 * p + 1], z = inp[3 * p + 2];

    if (s < 4) {
        float xn[3] = { (x / 1.5f + 1.0f) * 0.5f,
                        (y / 1.5f + 1.0f) * 0.5f,
                        (z / 1.5f + 1.0f) * 0.5f };
#pragma unroll 1
        for (int li = 0; li < 4; ++li) {
            int l = s * 4 + li;
            double scd   = exp2((7.0 * (double)l) / 15.0) * 16.0 - 1.0;
            float  scale = (float)scd;
            unsigned res = (unsigned)ceil(scd) + 1u;
            bool dense   = ((unsigned long long)res * res * res <= (unsigned long long)HASHMAP_SZ);
            unsigned pg[3]; float fr[3];
#pragma unroll
            for (int cc = 0; cc < 3; ++cc) {
                float pos = fmaf(xn[cc], scale, 0.5f);
                float pf  = floorf(pos);
                fr[cc] = pos - pf;
                pg[cc] = (unsigned)pf;
            }
            float wx[2] = {1.f - fr[0], fr[0]};
            float wy[2] = {1.f - fr[1], fr[1]};
            float wz[2] = {1.f - fr[2], fr[2]};
            const float2* tbl = (const float2*)table + (size_t)l * HASHMAP_SZ;
            float f0 = 0.f, f1 = 0.f;
#pragma unroll
            for (int cc = 0; cc < 8; ++cc) {
                unsigned gx = pg[0] + (unsigned)(cc & 1);
                unsigned gy = pg[1] + (unsigned)((cc >> 1) & 1);
                unsigned gz = pg[2] + (unsigned)((cc >> 2) & 1);
                unsigned idx;
                if (dense) idx = gx + gy * res + gz * res * res;
                else       idx = ((gx * 1u) ^ (gy * 2654435761u) ^ (gz * 805459861u)) & (HASHMAP_SZ - 1u);
                float w = (wx[cc & 1] * wy[(cc >> 1) & 1]) * wz[(cc >> 2) & 1];
                float2 t = tbl[idx];
                f0 = fmaf(w, t.x, f0);
                f1 = fmaf(w, t.y, f1);
            }
            xin[(198 + 2 * l) * P_PTS + p] = f0;
            xin[(199 + 2 * l) * P_PTS + p] = f1;
        }
    } else if (s == 4) {
        penc3(xin, p, 0, x, y, z);
    } else if (s == 5) {
        float wsum = stats[p];
        xin[63 * P_PTS + p] = wsum;
#pragma unroll
        for (int f = 0; f < 4; ++f) {
            float sn, co;
            sincosf(wsum * (float)(1 << f), &sn, &co);
            xin[(64 + 2 * f) * P_PTS + p] = sn;
            xin[(65 + 2 * f) * P_PTS + p] = co;
        }
        xin[230 * P_PTS + p] = 0.0f;
        xin[231 * P_PTS + p] = 0.0f;
    } else if (s == 6) {
        penc3(xin, p, 72, stats[1 * P_PTS + p], stats[2 * P_PTS + p], stats[3 * P_PTS + p]);
    } else {
        penc3(xin, p, 135, stats[4 * P_PTS + p], stats[5 * P_PTS + p], stats[6 * P_PTS + p]);
    }
}

// ---------------- fused transpose + bf16-split: xin -> g_x AND g_s ------------
__global__ void conv_tr2(const float* __restrict__ src,
                         __nv_bfloat16* __restrict__ dx,
                         __nv_bfloat16* __restrict__ ds)
{
    __shared__ float s[32][33];
    int tx = threadIdx.x, ty = threadIdx.y;
    int ct = blockIdx.x, pt = blockIdx.y;
#pragma unroll
    for (int r2 = 0; r2 < 4; ++r2) {
        int ci = ty + r2 * 8;
        int c = ct * 32 + ci;
        int p = pt * 32 + tx;
        s[ci][tx] = (c < 232) ? src[(size_t)c * P_PTS + p] : 0.0f;
    }
    __syncthreads();
#pragma unroll
    for (int r2 = 0; r2 < 4; ++r2) {
        int pi = ty + r2 * 8;
        int p = pt * 32 + pi;
        int c = ct * 32 + tx;
        float v = s[tx][pi];
        __nv_bfloat16 h = __float2bfloat16(v);
        dx[(size_t)p * 512 + c]       = h;
        dx[(size_t)p * 512 + 256 + c] = __float2bfloat16(v - __bfloat162float(h));
        if (c < 230) {
            float vs = v * INV_SQRT2;
            __nv_bfloat16 hs = __float2bfloat16(vs);
            ds[(size_t)p * 512 + c + 26]       = hs;
            ds[(size_t)p * 512 + 256 + c + 26] = __float2bfloat16(vs - __bfloat162float(hs));
        }
    }
}

// ---------------- fused persistent MLP: 512 threads, 32x32 warp tiles ---------
#define R_LOW0 0
#define R_LOW1 65536
#define R_HIGH 131072
#define R_W    196608
#define SMEM_FUSED 229376

__global__ __launch_bounds__(512, 1)
void fused_mlp(const __nv_bfloat16* __restrict__ gx,
               const __nv_bfloat16* __restrict__ gs,
               const __nv_bfloat16* __restrict__ gw,
               BPtrs bp, float* __restrict__ out)
{
    extern __shared__ __align__(16) char smem[];
    const uint32_t s0 = smem_u32(smem);
    const int tid = threadIdx.x, warp = tid >> 5, lane = tid & 31;
    const int wm = warp & 3, wn = warp >> 2;          // 4x4 warp grid
    const int m0 = blockIdx.x << 7;

    const int rbase = tid >> 2, cc = tid & 3;          // 512 thr = 128 rows x 4
    const uint32_t so0 = (uint32_t)(rbase * 64) +
                         (((uint32_t)cc ^ (((uint32_t)rbase >> 1) & 3)) << 4);

    const int lrow = lane & 15;
    const uint32_t lhi = (uint32_t)(lane >> 4);
    uint32_t rowA[2], rqA[2], rowB[2], rqB[2];
#pragma unroll
    for (int mi = 0; mi < 2; ++mi) {
        int R = wm * 32 + mi * 16 + lrow;
        rowA[mi] = (uint32_t)(R * 64); rqA[mi] = (uint32_t)((R >> 1) & 3);
    }
#pragma unroll
    for (int nb = 0; nb < 2; ++nb) {
        int R = wn * 32 + nb * 16 + lrow;
        rowB[nb] = (uint32_t)(R * 64); rqB[nb] = (uint32_t)((R >> 1) & 3);
    }

    auto load_full_act = [&](const __nv_bfloat16* src, uint32_t lowR) {
        const __nv_bfloat16* pS = src + (size_t)(m0 + rbase) * 512 + cc * 8;
#pragma unroll
        for (int kc = 0; kc < 8; ++kc) {
            uint32_t hiT = (kc < 4) ? (lowR + (uint32_t)kc * 8192)
                                    : (R_HIGH + (uint32_t)(kc - 4) * 8192);
            int k32 = kc << 5;
            cp16(s0 + hiT + so0,         pS + k32);
            cp16(s0 + hiT + 32768 + so0, pS + 256 + k32);
        }
    };
    auto load_w = [&](const __nv_bfloat16* Wl, int n0w, int kc, int stg) {
        const __nv_bfloat16* pW = Wl + (size_t)(n0w + rbase) * 512 + cc * 8;
        uint32_t wb = s0 + R_W + (uint32_t)stg * 16384;
        int k32 = kc << 5;
        cp16(wb + so0,        pW + k32);
        cp16(wb + 8192 + so0, pW + 256 + k32);
    };

    float c[2][4][4];
    uint32_t aF[3][8], bF[2][8];

    auto ldA = [&](int buf, uint32_t tile, int ks) {
        uint32_t ch = (uint32_t)(2 * ks) + lhi;
        ldsm4(&aF[buf][0], tile + rowA[0] + ((ch ^ rqA[0]) << 4));
        ldsm4(&aF[buf][4], tile + rowA[1] + ((ch ^ rqA[1]) << 4));
    };
    auto ldB = [&](int buf, uint32_t tile, int ks) {
        uint32_t ch = (uint32_t)(2 * ks) + lhi;
        ldsm4(&bF[buf][0], tile + rowB[0] + ((ch ^ rqB[0]) << 4));
        ldsm4(&bF[buf][4], tile + rowB[1] + ((ch ^ rqB[1]) << 4));
    };
    auto mmaBlk = [&](int abuf, int bbuf) {
#pragma unroll
        for (int mi = 0; mi < 2; ++mi)
#pragma unroll
            for (int nb = 0; nb < 2; ++nb) {
                mma16816(c[mi][nb * 2],     &aF[abuf][mi * 4],
                         bF[bbuf][nb * 4 + 0], bF[bbuf][nb * 4 + 2]);
                mma16816(c[mi][nb * 2 + 1], &aF[abuf][mi * 4],
                         bF[bbuf][nb * 4 + 1], bF[bbuf][nb * 4 + 3]);
            }
    };

    auto run_half = [&](const __nv_bfloat16* Wl, int n0w, uint32_t lowR) {
#pragma unroll
        for (int mi = 0; mi < 2; ++mi)
#pragma unroll
            for (int nf = 0; nf < 4; ++nf)
#pragma unroll
                for (int r = 0; r < 4; ++r) c[mi][nf][r] = 0.0f;
        load_w(Wl, n0w, 0, 0); CP_COMMIT();
#pragma unroll 1
        for (int kc = 0; kc < 8; ++kc) {
            CP_WAIT0();
            __syncthreads();
            if (kc + 1 < 8) { load_w(Wl, n0w, kc + 1, (kc + 1) & 1); CP_COMMIT(); }
            uint32_t tHI = s0 + ((kc < 4) ? (lowR + (uint32_t)kc * 8192)
                                          : (R_HIGH + (uint32_t)(kc - 4) * 8192));
            uint32_t tLO = tHI + 32768;
            uint32_t wst = s0 + R_W + (uint32_t)(kc & 1) * 16384;
            uint32_t wlo = wst + 8192;
            ldB(0, wst, 0);          // WHI0
            ldA(0, tHI, 0);          // AHI0 (cached)
            ldA(2, tLO, 0);          // ALO0
            mmaBlk(0, 0);            // s0
            ldB(1, wst, 1);          // WHI1
            ldA(1, tHI, 1);          // AHI1 (cached)
            mmaBlk(2, 0);            // s1
            ldA(2, tLO, 1);          // ALO1
            mmaBlk(1, 1);            // s2
            ldB(0, wlo, 0);          // WLO0
            mmaBlk(2, 1);            // s3
            ldB(1, wlo, 1);          // WLO1
            mmaBlk(0, 0);            // s4
            mmaBlk(1, 1);            // s5
        }
    };

    auto epi_smem = [&](uint32_t destR, const float* bias, int nb0, float os, int validN) {
#pragma unroll
        for (int mi = 0; mi < 2; ++mi)
#pragma unroll
            for (int nf = 0; nf < 4; ++nf) {
                int ncol = wn * 32 + nf * 8 + ((lane & 3) << 1);
                if (ncol >= validN) continue;
                float b0 = __ldg(bias + nb0 + ncol);
                float b1 = __ldg(bias + nb0 + ncol + 1);
                uint32_t chunk = (uint32_t)ncol >> 5;
                uint32_t cpos  = (uint32_t)ncol & 31;
#pragma unroll
                for (int r2 = 0; r2 < 2; ++r2) {
                    int row = wm * 32 + mi * 16 + (lane >> 2) + r2 * 8;
                    float v0 = softplus100(c[mi][nf][r2 * 2 + 0] + b0) * os;
                    float v1 = softplus100(c[mi][nf][r2 * 2 + 1] + b1) * os;
                    __nv_bfloat16 h0 = __float2bfloat16(v0);
                    __nv_bfloat16 h1 = __float2bfloat16(v1);
                    __nv_bfloat16 l0 = __float2bfloat16(v0 - __bfloat162float(h0));
                    __nv_bfloat16 l1 = __float2bfloat16(v1 - __bfloat162float(h1));
                    uint32_t hw = (uint32_t)__bfloat16_as_ushort(h0) |
                                  ((uint32_t)__bfloat16_as_ushort(h1) << 16);
                    uint32_t lw = (uint32_t)__bfloat16_as_ushort(l0) |
                                  ((uint32_t)__bfloat16_as_ushort(l1) << 16);
                    uint32_t off = (uint32_t)(row * 64) +
                                   (((cpos >> 3) ^ (((uint32_t)row >> 1) & 3)) << 4) +
                                   ((cpos & 7) << 1);
                    *(uint32_t*)(smem + destR + chunk * 8192 + off)         = hw;
                    *(uint32_t*)(smem + destR + 32768 + chunk * 8192 + off) = lw;
                }
            }
    };

    auto epi_gmem = [&](int n0w, const float* bias) {
#pragma unroll
        for (int mi = 0; mi < 2; ++mi)
#pragma unroll
            for (int nf = 0; nf < 4; ++nf) {
                int n = n0w + wn * 32 + nf * 8 + ((lane & 3) << 1);
                float b0 = __ldg(bias + n);
                float b1 = __ldg(bias + n + 1);
#pragma unroll
                for (int r2 = 0; r2 < 2; ++r2) {
                    int row = wm * 32 + mi * 16 + (lane >> 2) + r2 * 8;
                    size_t m = (size_t)(m0 + row);
                    out[m * 257 + n]     = c[mi][nf][r2 * 2 + 0] + b0;
                    out[m * 257 + n + 1] = c[mi][nf][r2 * 2 + 1] + b1;
                }
            }
    };

    // ---- initial activation load ----
    load_full_act(gx, R_LOW0); CP_COMMIT(); CP_WAIT0(); __syncthreads();
    uint32_t lowR = R_LOW0, altR = R_LOW1;
    const int wrow[9] = {0, 256, 512, 768, 896, 1152, 1408, 1664, 1920};

#pragma unroll 1
    for (int l = 0; l < 9; ++l) {
        const __nv_bfloat16* Wl = gw + (size_t)wrow[l] * 512;
        const float* bias = bp.b[l];
        if (l == 8) {
            run_half(Wl, 0, lowR);
            epi_gmem(0, bias);
            run_half(Wl, 128, lowR);
            epi_gmem(128, bias);
            // ---- column 256 via bf16x3 scalar dot from resident smem ----
            __syncthreads();
            if (tid < 256)
                ((uint32_t*)(smem + R_W))[tid] =
                    ((const uint32_t*)(gw + (size_t)2176 * 512))[tid];
            __syncthreads();
            {
                int r  = tid >> 2;           // 0..127
                int kq = tid & 3;            // 2 chunks each
                float acc = 0.0f;
                uint32_t rq = ((uint32_t)r >> 1) & 3;
#pragma unroll 1
                for (int c2 = 0; c2 < 2; ++c2) {
                    int kc = kq * 2 + c2;
                    uint32_t base = (kc < 4) ? (lowR + (uint32_t)kc * 8192)
                                             : (R_HIGH + (uint32_t)(kc - 4) * 8192);
#pragma unroll
                    for (int j = 0; j < 32; ++j) {
                        int col = kc * 32 + j;
                        uint32_t off = (uint32_t)(r * 64) +
                                       ((((uint32_t)j >> 3) ^ rq) << 4) + ((j & 7) << 1);
                        float ahi = __bfloat162float(*(__nv_bfloat16*)(smem + base + off));
                        float alo = __bfloat162float(*(__nv_bfloat16*)(smem + base + 32768 + off));
                        float whi = __bfloat162float(*(__nv_bfloat16*)(smem + R_W + col * 2));
                        float wlo = __bfloat162float(*(__nv_bfloat16*)(smem + R_W + 512 + col * 2));
                        acc = fmaf(ahi, whi, acc);
                        acc = fmaf(alo, whi, acc);
                        acc = fmaf(ahi, wlo, acc);
                    }
                }
                acc += __shfl_xor_sync(0xFFFFFFFFu, acc, 1);
                acc += __shfl_xor_sync(0xFFFFFFFFu, acc, 2);
                if (kq == 0)
                    out[(size_t)(m0 + r) * 257 + 256] = acc + __ldg(bias + 256);
            }
        } else if (l == 3) {
            run_half(Wl, 0, lowR);
            __syncthreads();
            load_full_act(gs, altR); CP_COMMIT(); CP_WAIT0(); __syncthreads();
            epi_smem(altR, bias, 0, INV_SQRT2, 26);
            __syncthreads();
            uint32_t t = lowR; lowR = altR; altR = t;
        } else {
            run_half(Wl, 0, lowR);
            epi_smem(altR, bias, 0, 1.0f, 128);
            run_half(Wl, 128, lowR);
            __syncthreads();
            epi_smem(R_HIGH, bias, 128, 1.0f, 128);
            __syncthreads();
            uint32_t t = lowR; lowR = altR; altR = t;
        }
    }
}

// ---------------- launch ------------------------------------------------------
extern "C" void kernel_launch(void* const* d_in, const int* in_sizes, int n_in,
                              void* d_out, int out_size)
{
    const float* inp   = (const float*)d_in[0];
    const float* parts = (const float*)d_in[1];
    const float* table = (const float*)d_in[2];
    WPtrs wp;
    BPtrs bp;
    for (int l = 0; l < 9; ++l) {
        wp.w[l] = (const float*)d_in[3 + 2 * l];
        bp.b[l] = (const float*)d_in[4 + 2 * l];
    }

    float *xin, *st;
    __nv_bfloat16 *xb, *sb, *wbase;
    cudaGetSymbolAddress((void**)&xin, g_xin);
    cudaGetSymbolAddress((void**)&st,  g_stats);
    cudaGetSymbolAddress((void**)&xb, g_x);
    cudaGetSymbolAddress((void**)&sb, g_s);
    cudaGetSymbolAddress((void**)&wbase, g_w);

    const int BQ_SMEM = (16384 + 2560) * 4;
    cudaFuncSetAttribute(fused_mlp, cudaFuncAttributeMaxDynamicSharedMemorySize, SMEM_FUSED);
    cudaFuncSetAttribute(ball_prep_kernel, cudaFuncAttributeMaxDynamicSharedMemorySize, BQ_SMEM);

    ball_prep_kernel<<<P_PTS / 32, 256, BQ_SMEM>>>(inp, parts, st, wp, wbase);  // idx 0
    encode_kernel<<<P_PTS / 32, 256>>>(inp, table, st, xin);                    // idx 1
    conv_tr2<<<dim3(8, P_PTS / 32), dim3(32, 8)>>>(xin, xb, sb);                // idx 2
    fused_mlp<<<P_PTS / 128, 512, SMEM_FUSED>>>(xb, sb, wbase, bp, (float*)d_out); // idx 3
}

// round 17
// speedup vs baseline: 1.0159x; 1.0001x over previous
#include <cuda_runtime.h>
#include <cuda_bf16.h>
#include <math.h>
#include <stdint.h>

#define P_PTS     16384
#define M_PART    4096
#define HASHMAP_SZ 524288u
#define NUM_LVL   16
#define INV_SQRT2 0.70710678118654752f

// ---------------- scratch (device globals; no allocation allowed) -------------
__device__ __align__(16) float g_stats[7 * P_PTS];
__device__ __align__(16) __nv_bfloat16 g_x[P_PTS * 512];
__device__ __align__(16) __nv_bfloat16 g_s[P_PTS * 512];   // skip input (cols 26..255)
__device__ __align__(16) __nv_bfloat16 g_w[2304 * 512];

// ---------------- PTX helpers -------------------------------------------------
static __device__ __forceinline__ uint32_t smem_u32(const void* p) {
    uint32_t a;
    asm("{ .reg .u64 t; cvta.to.shared.u64 t, %1; cvt.u32.u64 %0, t; }" : "=r"(a) : "l"(p));
    return a;
}
static __device__ __forceinline__ void cp16(uint32_t s, const void* g) {
    asm volatile("cp.async.ca.shared.global [%0], [%1], 16;" :: "r"(s), "l"(g));
}
#define CP_COMMIT()  asm volatile("cp.async.commit_group;" ::: "memory")
#define CP_WAIT0()   asm volatile("cp.async.wait_group 0;" ::: "memory")

static __device__ __forceinline__ void ldsm4(uint32_t* r, uint32_t a) {
    asm volatile("ldmatrix.sync.aligned.m8n8.x4.shared.b16 {%0,%1,%2,%3}, [%4];"
                 : "=r"(r[0]), "=r"(r[1]), "=r"(r[2]), "=r"(r[3]) : "r"(a));
}
static __device__ __forceinline__ void mma16816(float* c, const uint32_t* a,
                                                uint32_t b0, uint32_t b1) {
    asm volatile(
        "mma.sync.aligned.m16n8k16.row.col.f32.bf16.bf16.f32 "
        "{%0,%1,%2,%3}, {%4,%5,%6,%7}, {%8,%9}, {%0,%1,%2,%3};"
        : "+f"(c[0]), "+f"(c[1]), "+f"(c[2]), "+f"(c[3])
        : "r"(a[0]), "r"(a[1]), "r"(a[2]), "r"(a[3]), "r"(b0), "r"(b1));
}
static __device__ __forceinline__ float softplus100(float v) {
    float y = 100.0f * v;
    return (fmaxf(y, 0.0f) + __logf(1.0f + __expf(-fabsf(y)))) * 0.01f;
}

struct WPtrs { const float* w[9]; };
struct BPtrs { const float* b[9]; };

// ---------------- ball query (8x32 split) + fused weight prep -----------------
__global__ __launch_bounds__(256)
void ball_prep_kernel(const float* __restrict__ inp,
                      const float* __restrict__ parts,
                      float* __restrict__ stats,
                      WPtrs wp, __nv_bfloat16* __restrict__ wout)
{
    if (blockIdx.x < 256) {
        const int cum[10]  = {0, 256, 512, 768, 896, 1152, 1408, 1664, 1920, 2304};
        const int nout[9]  = {256, 256, 256, 26, 256, 256, 256, 256, 257};
        const int kact[9]  = {230, 256, 256, 256, 256, 256, 256, 256, 256};
        int gid = blockIdx.x * 256 + threadIdx.x;
#pragma unroll
        for (int t9 = 0; t9 < 9; ++t9) {
            int i = gid + t9 * 65536;
            int r = i >> 8, k = i & 255;
            int l = 0;
#pragma unroll
            for (int t = 1; t < 9; ++t) if (r >= cum[t]) l = t;
            int n = r - cum[l];
            float v = (n < nout[l] && k < kact[l]) ? wp.w[l][n * kact[l] + k] : 0.0f;
            __nv_bfloat16 h = __float2bfloat16(v);
            wout[(size_t)r * 512 + k]       = h;
            wout[(size_t)r * 512 + 256 + k] = __float2bfloat16(v - __bfloat162float(h));
        }
    }

    extern __shared__ float fsm[];
    float4* sp4 = (float4*)fsm;
    float*  ex  = fsm + 16384;
    int tid = threadIdx.x;
    for (int i = tid; i < M_PART; i += 256) {
        float px = parts[3 * i], py = parts[3 * i + 1], pz = parts[3 * i + 2];
        sp4[i] = make_float4(px, py, pz, (px * px + py * py) + pz * pz);
    }
    __syncthreads();

    const int c  = tid >> 5;
    const int pl = tid & 31;
    const int p  = blockIdx.x * 32 + pl;
    const float x = inp[3 * p], y = inp[3 * p + 1], z = inp[3 * p + 2];
    const float q1 = (x * x + y * y) + z * z;
    const float R2 = 0.01f;
    const int j0 = c << 9, j1 = j0 + 512;

    int h = 0;
    float wsum = 0.f, swx = 0.f, swy = 0.f, swz = 0.f;
    float sdx = 0.f, sdy = 0.f, sdz = 0.f;
    float s2x = 0.f, s2y = 0.f, s2z = 0.f;
#pragma unroll 8
    for (int j = j0; j < j1; ++j) {
        float4 q = sp4[j];
        float dot = x * q.x + y * q.y + z * q.z;
        float d2e = (q1 + q.w) - 2.0f * dot;
        if (d2e < R2) {
            ++h;
            float dx = q.x - x, dy = q.y - y, dz = q.z - z;
            float d2 = dx * dx + dy * dy + dz * dz;
            float d  = sqrtf(fmaxf(d2, 1e-24f));
            float dr = d / 0.1f;
            float w  = fmaxf(1.0f - dr * dr * dr, 0.0f);
            wsum += w;
            swx = fmaf(w, q.x, swx); swy = fmaf(w, q.y, swy); swz = fmaf(w, q.z, swz);
            sdx += dx; sdy += dy; sdz += dz;
            s2x = fmaf(dx, dx, s2x); s2y = fmaf(dy, dy, s2y); s2z = fmaf(dz, dz, s2z);
        }
    }
    ex[c * 32 + pl] = (float)h;
    __syncthreads();
    int start = 0, total = 0;
#pragma unroll
    for (int cc2 = 0; cc2 < 8; ++cc2) {
        int hv = (int)ex[cc2 * 32 + pl];
        if (cc2 < c) start += hv;
        total += hv;
    }
    int cnt    = min(32, total);
    int budget = max(0, min(32 - start, h));
    if (budget < h) {
        wsum = swx = swy = swz = 0.f;
        sdx = sdy = sdz = 0.f;
        s2x = s2y = s2z = 0.f;
        int taken = 0;
        for (int j = j0; j < j1 && taken < budget; ++j) {
            float4 q = sp4[j];
            float dot = x * q.x + y * q.y + z * q.z;
            float d2e = (q1 + q.w) - 2.0f * dot;
            if (d2e < R2) {
                ++taken;
                float dx = q.x - x, dy = q.y - y, dz = q.z - z;
                float d2 = dx * dx + dy * dy + dz * dz;
                float d  = sqrtf(fmaxf(d2, 1e-24f));
                float dr = d / 0.1f;
                float w  = fmaxf(1.0f - dr * dr * dr, 0.0f);
                wsum += w;
                swx = fmaf(w, q.x, swx); swy = fmaf(w, q.y, swy); swz = fmaf(w, q.z, swz);
                sdx += dx; sdy += dy; sdz += dz;
                s2x = fmaf(dx, dx, s2x); s2y = fmaf(dy, dy, s2y); s2z = fmaf(dz, dz, s2z);
            }
        }
    }
    __syncthreads();
    float part[10] = {wsum, swx, swy, swz, sdx, sdy, sdz, s2x, s2y, s2z};
#pragma unroll
    for (int f = 0; f < 10; ++f) ex[f * 256 + c * 32 + pl] = part[f];
    __syncthreads();

    if (c == 0) {
        float S[10];
#pragma unroll
        for (int f = 0; f < 10; ++f) {
            float acc = ex[f * 256 + pl];
#pragma unroll
            for (int cc2 = 1; cc2 < 8; ++cc2) acc += ex[f * 256 + cc2 * 32 + pl];
            S[f] = acc;
        }
        int ninv = 32 - cnt;
        if (ninv > 0) {
            float d  = sqrtf(fmaxf(q1, 1e-24f));
            float dr = d / 0.1f;
            float w  = fmaxf(1.0f - dr * dr * dr, 0.0f);
            S[0] += (float)ninv * w;
        }
        float nf  = (float)cnt;
        float wdn = S[0] + 1e-12f;
        float den = nf + 1e-12f;
        float vmx = S[4] / den, vmy = S[5] / den, vmz = S[6] / den;
        stats[0 * P_PTS + p] = S[0];
        stats[1 * P_PTS + p] = S[1] / wdn;
        stats[2 * P_PTS + p] = S[2] / wdn;
        stats[3 * P_PTS + p] = S[3] / wdn;
        stats[4 * P_PTS + p] = (S[7] - 2.0f * vmx * S[4] + nf * vmx * vmx) / den;
        stats[5 * P_PTS + p] = (S[8] - 2.0f * vmy * S[5] + nf * vmy * vmy) / den;
        stats[6 * P_PTS + p] = (S[9] - 2.0f * vmz * S[6] + nf * vmz * vmz) / den;
    }
}

// ---------------- encode fused: features -> smem -> bf16 hi/lo direct ---------
// sincos via two bases (f=0, f=5) + 4 angle doublings each: err <= ~2e-6 abs.
__device__ __forceinline__ void penc3_sm(float (*sm)[233], int pl, int base,
                                         float a, float b, float c)
{
    float v[3] = {a, b, c};
#pragma unroll
    for (int ch = 0; ch < 3; ++ch) {
        sm[pl][base + ch] = v[ch];
        float sn, cs;
        sincosf(v[ch], &sn, &cs);
        sm[pl][base + 3 + ch]     = sn;
        sm[pl][base + 3 + 3 + ch] = cs;
#pragma unroll
        for (int f = 1; f < 5; ++f) {
            float s2 = 2.0f * sn * cs;
            float c2 = cs * cs - sn * sn;
            sn = s2; cs = c2;
            sm[pl][base + 3 + f * 6 + ch]     = sn;
            sm[pl][base + 3 + f * 6 + 3 + ch] = cs;
        }
        sincosf(v[ch] * 32.0f, &sn, &cs);
        sm[pl][base + 3 + 5 * 6 + ch]     = sn;
        sm[pl][base + 3 + 5 * 6 + 3 + ch] = cs;
#pragma unroll
        for (int f = 6; f < 10; ++f) {
            float s2 = 2.0f * sn * cs;
            float c2 = cs * cs - sn * sn;
            sn = s2; cs = c2;
            sm[pl][base + 3 + f * 6 + ch]     = sn;
            sm[pl][base + 3 + f * 6 + 3 + ch] = cs;
        }
    }
}

__global__ __launch_bounds__(256)
void encode_kernel(const float* __restrict__ inp,
                   const float* __restrict__ table,
                   const float* __restrict__ stats,
                   __nv_bfloat16* __restrict__ gx,
                   __nv_bfloat16* __restrict__ gs)
{
    __shared__ float sm[32][233];
    int tid = threadIdx.x;
    int pl = tid & 31, s = tid >> 5;
    int p = blockIdx.x * 32 + pl;
    float x = inp[3 * p], y = inp[3 * p + 1], z = inp[3 * p + 2];

    if (s < 4) {
        float xn[3] = { (x / 1.5f + 1.0f) * 0.5f,
                        (y / 1.5f + 1.0f) * 0.5f,
                        (z / 1.5f + 1.0f) * 0.5f };
#pragma unroll 1
        for (int li = 0; li < 4; ++li) {
            int l = s * 4 + li;
            double scd   = exp2((7.0 * (double)l) / 15.0) * 16.0 - 1.0;
            float  scale = (float)scd;
            unsigned res = (unsigned)ceil(scd) + 1u;
            bool dense   = ((unsigned long long)res * res * res <= (unsigned long long)HASHMAP_SZ);
            unsigned pg[3]; float fr[3];
#pragma unroll
            for (int cc = 0; cc < 3; ++cc) {
                float pos = fmaf(xn[cc], scale, 0.5f);
                float pf  = floorf(pos);
                fr[cc] = pos - pf;
                pg[cc] = (unsigned)pf;
            }
            float wx[2] = {1.f - fr[0], fr[0]};
            float wy[2] = {1.f - fr[1], fr[1]};
            float wz[2] = {1.f - fr[2], fr[2]};
            const float2* tbl = (const float2*)table + (size_t)l * HASHMAP_SZ;
            float f0 = 0.f, f1 = 0.f;
#pragma unroll
            for (int cc = 0; cc < 8; ++cc) {
                unsigned gxi = pg[0] + (unsigned)(cc & 1);
                unsigned gyi = pg[1] + (unsigned)((cc >> 1) & 1);
                unsigned gzi = pg[2] + (unsigned)((cc >> 2) & 1);
                unsigned idx;
                if (dense) idx = gxi + gyi * res + gzi * res * res;
                else       idx = ((gxi * 1u) ^ (gyi * 2654435761u) ^ (gzi * 805459861u)) & (HASHMAP_SZ - 1u);
                float w = (wx[cc & 1] * wy[(cc >> 1) & 1]) * wz[(cc >> 2) & 1];
                float2 t = tbl[idx];
                f0 = fmaf(w, t.x, f0);
                f1 = fmaf(w, t.y, f1);
            }
            sm[pl][198 + 2 * l] = f0;
            sm[pl][199 + 2 * l] = f1;
        }
    } else if (s == 4) {
        penc3_sm(sm, pl, 0, x, y, z);
    } else if (s == 5) {
        float wsum = stats[p];
        sm[pl][63] = wsum;
        float sn, cs;
        sincosf(wsum, &sn, &cs);
        sm[pl][64] = sn; sm[pl][65] = cs;
#pragma unroll
        for (int f = 1; f < 4; ++f) {
            float s2 = 2.0f * sn * cs;
            float c2 = cs * cs - sn * sn;
            sn = s2; cs = c2;
            sm[pl][64 + 2 * f] = sn;
            sm[pl][65 + 2 * f] = cs;
        }
    } else if (s == 6) {
        penc3_sm(sm, pl, 72, stats[1 * P_PTS + p], stats[2 * P_PTS + p], stats[3 * P_PTS + p]);
    } else {
        penc3_sm(sm, pl, 135, stats[4 * P_PTS + p], stats[5 * P_PTS + p], stats[6 * P_PTS + p]);
    }
    __syncthreads();

    // ---- writer phase: coalesced bf16 hi/lo row-major to g_x and g_s ----
    const int p0 = blockIdx.x * 32;
#pragma unroll 1
    for (int q = tid; q < 32 * 128; q += 256) {
        int row = q >> 7, cp = q & 127, ccol = cp * 2;
        size_t basep = (size_t)(p0 + row) * 512;
        float v0 = (ccol     < 230) ? sm[row][ccol]     : 0.0f;
        float v1 = (ccol + 1 < 230) ? sm[row][ccol + 1] : 0.0f;
        __nv_bfloat16 h0 = __float2bfloat16(v0);
        __nv_bfloat16 h1 = __float2bfloat16(v1);
        __nv_bfloat16 l0 = __float2bfloat16(v0 - __bfloat162float(h0));
        __nv_bfloat16 l1 = __float2bfloat16(v1 - __bfloat162float(h1));
        *(uint32_t*)(gx + basep + ccol) =
            (uint32_t)__bfloat16_as_ushort(h0) | ((uint32_t)__bfloat16_as_ushort(h1) << 16);
        *(uint32_t*)(gx + basep + 256 + ccol) =
            (uint32_t)__bfloat16_as_ushort(l0) | ((uint32_t)__bfloat16_as_ushort(l1) << 16);
        if (ccol >= 26) {
            float w0 = sm[row][ccol - 26] * INV_SQRT2;
            float w1 = sm[row][ccol - 25] * INV_SQRT2;
            __nv_bfloat16 g0 = __float2bfloat16(w0);
            __nv_bfloat16 g1 = __float2bfloat16(w1);
            __nv_bfloat16 m0 = __float2bfloat16(w0 - __bfloat162float(g0));
            __nv_bfloat16 m1 = __float2bfloat16(w1 - __bfloat162float(g1));
            *(uint32_t*)(gs + basep + ccol) =
                (uint32_t)__bfloat16_as_ushort(g0) | ((uint32_t)__bfloat16_as_ushort(g1) << 16);
            *(uint32_t*)(gs + basep + 256 + ccol) =
                (uint32_t)__bfloat16_as_ushort(m0) | ((uint32_t)__bfloat16_as_ushort(m1) << 16);
        }
    }
}

// ---------------- fused persistent MLP: 512 threads, 32x32 warp tiles ---------
#define R_LOW0 0
#define R_LOW1 65536
#define R_HIGH 131072
#define R_W    196608
#define SMEM_FUSED 229376

__global__ __launch_bounds__(512, 1)
void fused_mlp(const __nv_bfloat16* __restrict__ gx,
               const __nv_bfloat16* __restrict__ gs,
               const __nv_bfloat16* __restrict__ gw,
               BPtrs bp, float* __restrict__ out)
{
    extern __shared__ __align__(16) char smem[];
    const uint32_t s0 = smem_u32(smem);
    const int tid = threadIdx.x, warp = tid >> 5, lane = tid & 31;
    const int wm = warp & 3, wn = warp >> 2;
    const int m0 = blockIdx.x << 7;

    const int rbase = tid >> 2, cc = tid & 3;
    const uint32_t so0 = (uint32_t)(rbase * 64) +
                         (((uint32_t)cc ^ (((uint32_t)rbase >> 1) & 3)) << 4);

    const int lrow = lane & 15;
    const uint32_t lhi = (uint32_t)(lane >> 4);
    uint32_t rowA[2], rqA[2], rowB[2], rqB[2];
#pragma unroll
    for (int mi = 0; mi < 2; ++mi) {
        int R = wm * 32 + mi * 16 + lrow;
        rowA[mi] = (uint32_t)(R * 64); rqA[mi] = (uint32_t)((R >> 1) & 3);
    }
#pragma unroll
    for (int nb = 0; nb < 2; ++nb) {
        int R = wn * 32 + nb * 16 + lrow;
        rowB[nb] = (uint32_t)(R * 64); rqB[nb] = (uint32_t)((R >> 1) & 3);
    }

    auto load_full_act = [&](const __nv_bfloat16* src, uint32_t lowR) {
        const __nv_bfloat16* pS = src + (size_t)(m0 + rbase) * 512 + cc * 8;
#pragma unroll
        for (int kc = 0; kc < 8; ++kc) {
            uint32_t hiT = (kc < 4) ? (lowR + (uint32_t)kc * 8192)
                                    : (R_HIGH + (uint32_t)(kc - 4) * 8192);
            int k32 = kc << 5;
            cp16(s0 + hiT + so0,         pS + k32);
            cp16(s0 + hiT + 32768 + so0, pS + 256 + k32);
        }
    };
    auto load_w = [&](const __nv_bfloat16* Wl, int n0w, int kc, int stg) {
        const __nv_bfloat16* pW = Wl + (size_t)(n0w + rbase) * 512 + cc * 8;
        uint32_t wb = s0 + R_W + (uint32_t)stg * 16384;
        int k32 = kc << 5;
        cp16(wb + so0,        pW + k32);
        cp16(wb + 8192 + so0, pW + 256 + k32);
    };

    float c[2][4][4];
    uint32_t aF[3][8], bF[2][8];

    auto ldA = [&](int buf, uint32_t tile, int ks) {
        uint32_t ch = (uint32_t)(2 * ks) + lhi;
        ldsm4(&aF[buf][0], tile + rowA[0] + ((ch ^ rqA[0]) << 4));
        ldsm4(&aF[buf][4], tile + rowA[1] + ((ch ^ rqA[1]) << 4));
    };
    auto ldB = [&](int buf, uint32_t tile, int ks) {
        uint32_t ch = (uint32_t)(2 * ks) + lhi;
        ldsm4(&bF[buf][0], tile + rowB[0] + ((ch ^ rqB[0]) << 4));
        ldsm4(&bF[buf][4], tile + rowB[1] + ((ch ^ rqB[1]) << 4));
    };
    auto mmaBlk = [&](int abuf, int bbuf) {
#pragma unroll
        for (int mi = 0; mi < 2; ++mi)
#pragma unroll
            for (int nb = 0; nb < 2; ++nb) {
                mma16816(c[mi][nb * 2],     &aF[abuf][mi * 4],
                         bF[bbuf][nb * 4 + 0], bF[bbuf][nb * 4 + 2]);
                mma16816(c[mi][nb * 2 + 1], &aF[abuf][mi * 4],
                         bF[bbuf][nb * 4 + 1], bF[bbuf][nb * 4 + 3]);
            }
    };

    auto run_half = [&](const __nv_bfloat16* Wl, int n0w, uint32_t lowR) {
#pragma unroll
        for (int mi = 0; mi < 2; ++mi)
#pragma unroll
            for (int nf = 0; nf < 4; ++nf)
#pragma unroll
                for (int r = 0; r < 4; ++r) c[mi][nf][r] = 0.0f;
        load_w(Wl, n0w, 0, 0); CP_COMMIT();
#pragma unroll 1
        for (int kc = 0; kc < 8; ++kc) {
            CP_WAIT0();
            __syncthreads();
            if (kc + 1 < 8) { load_w(Wl, n0w, kc + 1, (kc + 1) & 1); CP_COMMIT(); }
            uint32_t tHI = s0 + ((kc < 4) ? (lowR + (uint32_t)kc * 8192)
                                          : (R_HIGH + (uint32_t)(kc - 4) * 8192));
            uint32_t tLO = tHI + 32768;
            uint32_t wst = s0 + R_W + (uint32_t)(kc & 1) * 16384;
            uint32_t wlo = wst + 8192;
            ldB(0, wst, 0);
            ldA(0, tHI, 0);
            ldA(2, tLO, 0);
            mmaBlk(0, 0);
            ldB(1, wst, 1);
            ldA(1, tHI, 1);
            mmaBlk(2, 0);
            ldA(2, tLO, 1);
            mmaBlk(1, 1);
            ldB(0, wlo, 0);
            mmaBlk(2, 1);
            ldB(1, wlo, 1);
            mmaBlk(0, 0);
            mmaBlk(1, 1);
        }
    };

    auto epi_smem = [&](uint32_t destR, const float* bias, int nb0, float os, int validN) {
#pragma unroll
        for (int mi = 0; mi < 2; ++mi)
#pragma unroll
            for (int nf = 0; nf < 4; ++nf) {
                int ncol = wn * 32 + nf * 8 + ((lane & 3) << 1);
                if (ncol >= validN) continue;
                float b0 = __ldg(bias + nb0 + ncol);
                float b1 = __ldg(bias + nb0 + ncol + 1);
                uint32_t chunk = (uint32_t)ncol >> 5;
                uint32_t cpos  = (uint32_t)ncol & 31;
#pragma unroll
                for (int r2 = 0; r2 < 2; ++r2) {
                    int row = wm * 32 + mi * 16 + (lane >> 2) + r2 * 8;
                    float v0 = softplus100(c[mi][nf][r2 * 2 + 0] + b0) * os;
                    float v1 = softplus100(c[mi][nf][r2 * 2 + 1] + b1) * os;
                    __nv_bfloat16 h0 = __float2bfloat16(v0);
                    __nv_bfloat16 h1 = __float2bfloat16(v1);
                    __nv_bfloat16 l0 = __float2bfloat16(v0 - __bfloat162float(h0));
                    __nv_bfloat16 l1 = __float2bfloat16(v1 - __bfloat162float(h1));
                    uint32_t hw = (uint32_t)__bfloat16_as_ushort(h0) |
                                  ((uint32_t)__bfloat16_as_ushort(h1) << 16);
                    uint32_t lw = (uint32_t)__bfloat16_as_ushort(l0) |
                                  ((uint32_t)__bfloat16_as_ushort(l1) << 16);
                    uint32_t off = (uint32_t)(row * 64) +
                                   (((cpos >> 3) ^ (((uint32_t)row >> 1) & 3)) << 4) +
                                   ((cpos & 7) << 1);
                    *(uint32_t*)(smem + destR + chunk * 8192 + off)         = hw;
                    *(uint32_t*)(smem + destR + 32768 + chunk * 8192 + off) = lw;
                }
            }
    };

    auto epi_gmem = [&](int n0w, const float* bias) {
#pragma unroll
        for (int mi = 0; mi < 2; ++mi)
#pragma unroll
            for (int nf = 0; nf < 4; ++nf) {
                int n = n0w + wn * 32 + nf * 8 + ((lane & 3) << 1);
                float b0 = __ldg(bias + n);
                float b1 = __ldg(bias + n + 1);
#pragma unroll
                for (int r2 = 0; r2 < 2; ++r2) {
                    int row = wm * 32 + mi * 16 + (lane >> 2) + r2 * 8;
                    size_t m = (size_t)(m0 + row);
                    out[m * 257 + n]     = c[mi][nf][r2 * 2 + 0] + b0;
                    out[m * 257 + n + 1] = c[mi][nf][r2 * 2 + 1] + b1;
                }
            }
    };

    // ---- initial activation load ----
    load_full_act(gx, R_LOW0); CP_COMMIT(); CP_WAIT0(); __syncthreads();
    uint32_t lowR = R_LOW0, altR = R_LOW1;
    const int wrow[9] = {0, 256, 512, 768, 896, 1152, 1408, 1664, 1920};

#pragma unroll 1
    for (int l = 0; l < 9; ++l) {
        const __nv_bfloat16* Wl = gw + (size_t)wrow[l] * 512;
        const float* bias = bp.b[l];
        if (l == 8) {
            run_half(Wl, 0, lowR);
            epi_gmem(0, bias);
            run_half(Wl, 128, lowR);
            epi_gmem(128, bias);
            __syncthreads();
            if (tid < 256)
                ((uint32_t*)(smem + R_W))[tid] =
                    ((const uint32_t*)(gw + (size_t)2176 * 512))[tid];
            __syncthreads();
            {
                int r  = tid >> 2;
                int kq = tid & 3;
                float acc = 0.0f;
                uint32_t rq = ((uint32_t)r >> 1) & 3;
#pragma unroll 1
                for (int c2 = 0; c2 < 2; ++c2) {
                    int kc = kq * 2 + c2;
                    uint32_t base = (kc < 4) ? (lowR + (uint32_t)kc * 8192)
                                             : (R_HIGH + (uint32_t)(kc - 4) * 8192);
#pragma unroll
                    for (int j = 0; j < 32; ++j) {
                        int col = kc * 32 + j;
                        uint32_t off = (uint32_t)(r * 64) +
                                       ((((uint32_t)j >> 3) ^ rq) << 4) + ((j & 7) << 1);
                        float ahi = __bfloat162float(*(__nv_bfloat16*)(smem + base + off));
                        float alo = __bfloat162float(*(__nv_bfloat16*)(smem + base + 32768 + off));
                        float whi = __bfloat162float(*(__nv_bfloat16*)(smem + R_W + col * 2));
                        float wlo = __bfloat162float(*(__nv_bfloat16*)(smem + R_W + 512 + col * 2));
                        acc = fmaf(ahi, whi, acc);
                        acc = fmaf(alo, whi, acc);
                        acc = fmaf(ahi, wlo, acc);
                    }
                }
                acc += __shfl_xor_sync(0xFFFFFFFFu, acc, 1);
                acc += __shfl_xor_sync(0xFFFFFFFFu, acc, 2);
                if (kq == 0)
                    out[(size_t)(m0 + r) * 257 + 256] = acc + __ldg(bias + 256);
            }
        } else if (l == 3) {
            run_half(Wl, 0, lowR);
            __syncthreads();
            load_full_act(gs, altR); CP_COMMIT(); CP_WAIT0(); __syncthreads();
            epi_smem(altR, bias, 0, INV_SQRT2, 26);
            __syncthreads();
            uint32_t t = lowR; lowR = altR; altR = t;
        } else {
            run_half(Wl, 0, lowR);
            epi_smem(altR, bias, 0, 1.0f, 128);
            run_half(Wl, 128, lowR);
            __syncthreads();
            epi_smem(R_HIGH, bias, 128, 1.0f, 128);
            __syncthreads();
            uint32_t t = lowR; lowR = altR; altR = t;
        }
    }
}

// ---------------- launch ------------------------------------------------------
extern "C" void kernel_launch(void* const* d_in, const int* in_sizes, int n_in,
                              void* d_out, int out_size)
{
    const float* inp   = (const float*)d_in[0];
    const float* parts = (const float*)d_in[1];
    const float* table = (const float*)d_in[2];
    WPtrs wp;
    BPtrs bp;
    for (int l = 0; l < 9; ++l) {
        wp.w[l] = (const float*)d_in[3 + 2 * l];
        bp.b[l] = (const float*)d_in[4 + 2 * l];
    }

    float* st;
    __nv_bfloat16 *xb, *sb, *wbase;
    cudaGetSymbolAddress((void**)&st,  g_stats);
    cudaGetSymbolAddress((void**)&xb, g_x);
    cudaGetSymbolAddress((void**)&sb, g_s);
    cudaGetSymbolAddress((void**)&wbase, g_w);

    const int BQ_SMEM = (16384 + 2560) * 4;
    cudaFuncSetAttribute(fused_mlp, cudaFuncAttributeMaxDynamicSharedMemorySize, SMEM_FUSED);
    cudaFuncSetAttribute(ball_prep_kernel, cudaFuncAttributeMaxDynamicSharedMemorySize, BQ_SMEM);

    ball_prep_kernel<<<P_PTS / 32, 256, BQ_SMEM>>>(inp, parts, st, wp, wbase);     // idx 0
    encode_kernel<<<P_PTS / 32, 256>>>(inp, table, st, xb, sb);                    // idx 1
    fused_mlp<<<P_PTS / 128, 512, SMEM_FUSED>>>(xb, sb, wbase, bp, (float*)d_out); // idx 2
}